// round 1
// baseline (speedup 1.0000x reference)
#include <cuda_runtime.h>
#include <cuda_bf16.h>
#include <stdint.h>

// Problem constants
#define NWIN   512      // 8 batch * 8 * 8 windows
#define T_     64       // tokens per window
#define C_     512      // channels
#define NH_    8
#define D_     64
#define HD_    512      // NH_*D_
#define SCALE_ 0.125f   // 1/sqrt(64)

// ---------------- scratch (static __device__, allocation-guard safe) ----------------
__device__ __nv_bfloat16 g_q [NWIN * T_ * HD_];
__device__ __nv_bfloat16 g_k [NWIN * T_ * HD_];
__device__ __nv_bfloat16 g_v [NWIN * T_ * HD_];
__device__ __nv_bfloat16 g_o [NWIN * T_ * HD_];
__device__ __nv_bfloat16 g_wqT[HD_ * C_];   // [hd][c]  (transposed)
__device__ __nv_bfloat16 g_wkT[HD_ * C_];
__device__ __nv_bfloat16 g_wvT[HD_ * C_];
__device__ __nv_bfloat16 g_woT[C_ * HD_];   // [c][hd]  (transposed)

// ---------------- helpers ----------------
__device__ __forceinline__ void mma16816(float* c, uint32_t a0, uint32_t a1, uint32_t a2, uint32_t a3,
                                         uint32_t b0, uint32_t b1) {
    asm volatile(
        "mma.sync.aligned.m16n8k16.row.col.f32.bf16.bf16.f32 "
        "{%0,%1,%2,%3}, {%4,%5,%6,%7}, {%8,%9}, {%0,%1,%2,%3};"
        : "+f"(c[0]), "+f"(c[1]), "+f"(c[2]), "+f"(c[3])
        : "r"(a0), "r"(a1), "r"(a2), "r"(a3), "r"(b0), "r"(b1));
}

__device__ __forceinline__ uint32_t pack_bf16(float a, float b) {
    __nv_bfloat162 t = __floats2bfloat162_rn(a, b);
    return *reinterpret_cast<uint32_t*>(&t);
}

// ---------------- K0: weight convert + transpose ----------------
__global__ void convert_weights(const float* __restrict__ wq, const float* __restrict__ wk,
                                const float* __restrict__ wv, const float* __restrict__ wo) {
    int idx = blockIdx.x * blockDim.x + threadIdx.x;   // 0 .. 262143
    if (idx >= C_ * HD_) return;
    int r = idx >> 9;      // row of source matrix (c for wq/wk/wv, hd for wo)
    int j = idx & 511;     // col of source matrix
    g_wqT[j * C_ + r] = __float2bfloat16(wq[idx]);
    g_wkT[j * C_ + r] = __float2bfloat16(wk[idx]);
    g_wvT[j * C_ + r] = __float2bfloat16(wv[idx]);
    g_woT[j * HD_ + r] = __float2bfloat16(wo[idx]);    // wo[hd][c] -> [c][hd]
}

// ---------------- K1: gather(window+roll) + QKV projection ----------------
// grid: (12, 512)  blockIdx.x: colTile (0..11) -> sel = /4 (q/k/v), 128 cols each
// block: 256 threads (8 warps, layout 4x2 warp tiles of 16x64)
__global__ __launch_bounds__(256) void qkv_kernel(const float* __restrict__ x,
                                                  const float* __restrict__ bq,
                                                  const float* __restrict__ bk,
                                                  const float* __restrict__ bv) {
    __shared__ __nv_bfloat16 As[64 * 72];
    __shared__ __nv_bfloat16 Bs[128 * 72];
    __shared__ int rowoff[64];

    const int n  = blockIdx.y;
    const int ct = blockIdx.x;
    const int sel = ct >> 2;
    const int colbase = (ct & 3) * 128;

    const __nv_bfloat16* W = (sel == 0) ? g_wqT : (sel == 1) ? g_wkT : g_wvT;
    const float* bias      = (sel == 0) ? bq    : (sel == 1) ? bk    : bv;
    __nv_bfloat16* outp    = (sel == 0) ? g_q   : (sel == 1) ? g_k   : g_v;

    const int tid  = threadIdx.x;
    const int lane = tid & 31;
    const int warp = tid >> 5;
    const int g    = lane >> 2;
    const int tg   = lane & 3;
    const int wm   = warp >> 1;     // 0..3 -> rows 16*wm
    const int wn   = warp & 1;      // 0..1 -> cols 64*wn

    const int b  = n >> 6;
    const int wh = (n >> 3) & 7;
    const int ww = n & 7;
    if (tid < 64) {
        int i = tid >> 3, j = tid & 7;
        int r  = (wh * 8 + i + 4) & 63;
        int cc = (ww * 8 + j + 4) & 63;
        rowoff[tid] = ((b * 64 + r) * 64 + cc) * C_;
    }
    __syncthreads();

    float acc[8][4];
    #pragma unroll
    for (int nt = 0; nt < 8; nt++) { acc[nt][0]=0.f; acc[nt][1]=0.f; acc[nt][2]=0.f; acc[nt][3]=0.f; }

    for (int kc = 0; kc < 8; kc++) {
        if (kc) __syncthreads();
        // A: 64 tokens x 64 fp32 -> bf16, gathered
        {
            int row = tid >> 2, quad = tid & 3;
            const float4* src = reinterpret_cast<const float4*>(x + rowoff[row] + kc * 64 + quad * 16);
            __nv_bfloat16* dst = As + row * 72 + quad * 16;
            #pragma unroll
            for (int e = 0; e < 4; e++) {
                float4 f = src[e];
                *reinterpret_cast<__nv_bfloat162*>(dst + e * 4)     = __floats2bfloat162_rn(f.x, f.y);
                *reinterpret_cast<__nv_bfloat162*>(dst + e * 4 + 2) = __floats2bfloat162_rn(f.z, f.w);
            }
        }
        // B: 128 out-cols x 64 k, from pre-transposed weights [hd][c]
        {
            #pragma unroll
            for (int e = 0; e < 4; e++) {
                int it = tid + e * 256;   // 0..1023
                int rn = it >> 3, seg = it & 7;
                *reinterpret_cast<uint4*>(Bs + rn * 72 + seg * 8) =
                    *reinterpret_cast<const uint4*>(W + (colbase + rn) * C_ + kc * 64 + seg * 8);
            }
        }
        __syncthreads();
        #pragma unroll
        for (int ks = 0; ks < 4; ks++) {
            const int ar0 = wm * 16 + g;
            const int kcol = ks * 16 + 2 * tg;
            uint32_t a0 = *reinterpret_cast<const uint32_t*>(As + ar0 * 72 + kcol);
            uint32_t a1 = *reinterpret_cast<const uint32_t*>(As + (ar0 + 8) * 72 + kcol);
            uint32_t a2 = *reinterpret_cast<const uint32_t*>(As + ar0 * 72 + kcol + 8);
            uint32_t a3 = *reinterpret_cast<const uint32_t*>(As + (ar0 + 8) * 72 + kcol + 8);
            #pragma unroll
            for (int nt = 0; nt < 8; nt++) {
                int bn = wn * 64 + nt * 8 + g;
                uint32_t b0 = *reinterpret_cast<const uint32_t*>(Bs + bn * 72 + kcol);
                uint32_t b1 = *reinterpret_cast<const uint32_t*>(Bs + bn * 72 + kcol + 8);
                mma16816(acc[nt], a0, a1, a2, a3, b0, b1);
            }
        }
    }
    // epilogue: +bias, bf16 store to scratch [n][t][col]
    const int r0 = wm * 16 + g;
    const int base = n * T_ * HD_;
    #pragma unroll
    for (int nt = 0; nt < 8; nt++) {
        int col = colbase + wn * 64 + nt * 8 + 2 * tg;
        float b0f = bias[col], b1f = bias[col + 1];
        *reinterpret_cast<uint32_t*>(outp + base + r0 * HD_ + col)       = pack_bf16(acc[nt][0] + b0f, acc[nt][1] + b1f);
        *reinterpret_cast<uint32_t*>(outp + base + (r0 + 8) * HD_ + col) = pack_bf16(acc[nt][2] + b0f, acc[nt][3] + b1f);
    }
}

// ---------------- K2: attention per (window, head) ----------------
// grid: 4096 = 512 windows * 8 heads.  block: 128 threads (4 warps, 16 q-rows each)
__global__ __launch_bounds__(128) void attn_kernel() {
    __shared__ __nv_bfloat16 Qs[64 * 72];
    __shared__ __nv_bfloat16 Ks[64 * 72];
    __shared__ __nv_bfloat16 Vt[64 * 72];   // transposed: [d][token]

    const int nh = blockIdx.x;
    const int n = nh >> 3, h = nh & 7;
    const int tid = threadIdx.x, lane = tid & 31, warp = tid >> 5;
    const int g = lane >> 2, tg = lane & 3;

    const int base = n * T_ * HD_ + h * D_;
    // loads: 64 rows x 8 uint4 each = 512 uint4 per tensor, 4 per thread
    #pragma unroll
    for (int e = 0; e < 4; e++) {
        int it = tid + e * 128;
        int row = it >> 3, seg = it & 7;
        *reinterpret_cast<uint4*>(Qs + row * 72 + seg * 8) =
            *reinterpret_cast<const uint4*>(g_q + base + row * HD_ + seg * 8);
        *reinterpret_cast<uint4*>(Ks + row * 72 + seg * 8) =
            *reinterpret_cast<const uint4*>(g_k + base + row * HD_ + seg * 8);
        uint4 vv = *reinterpret_cast<const uint4*>(g_v + base + row * HD_ + seg * 8);
        const unsigned short* vs = reinterpret_cast<const unsigned short*>(&vv);
        #pragma unroll
        for (int d = 0; d < 8; d++)
            reinterpret_cast<unsigned short*>(Vt)[(seg * 8 + d) * 72 + row] = vs[d];
    }
    __syncthreads();

    // scores = Q K^T  (16 rows per warp x 64 cols)
    float sc[8][4];
    #pragma unroll
    for (int nt = 0; nt < 8; nt++) { sc[nt][0]=0.f; sc[nt][1]=0.f; sc[nt][2]=0.f; sc[nt][3]=0.f; }
    const int r0 = warp * 16 + g;
    #pragma unroll
    for (int ks = 0; ks < 4; ks++) {
        const int kcol = ks * 16 + 2 * tg;
        uint32_t a0 = *reinterpret_cast<const uint32_t*>(Qs + r0 * 72 + kcol);
        uint32_t a1 = *reinterpret_cast<const uint32_t*>(Qs + (r0 + 8) * 72 + kcol);
        uint32_t a2 = *reinterpret_cast<const uint32_t*>(Qs + r0 * 72 + kcol + 8);
        uint32_t a3 = *reinterpret_cast<const uint32_t*>(Qs + (r0 + 8) * 72 + kcol + 8);
        #pragma unroll
        for (int nt = 0; nt < 8; nt++) {
            uint32_t b0 = *reinterpret_cast<const uint32_t*>(Ks + (nt * 8 + g) * 72 + kcol);
            uint32_t b1 = *reinterpret_cast<const uint32_t*>(Ks + (nt * 8 + g) * 72 + kcol + 8);
            mma16816(sc[nt], a0, a1, a2, a3, b0, b1);
        }
    }

    // softmax over 64 keys. thread holds 16 vals of row r0 (c0,c1) and 16 of row r0+8 (c2,c3)
    float mx0 = -1e30f, mx1 = -1e30f;
    #pragma unroll
    for (int nt = 0; nt < 8; nt++) {
        mx0 = fmaxf(mx0, fmaxf(sc[nt][0], sc[nt][1]));
        mx1 = fmaxf(mx1, fmaxf(sc[nt][2], sc[nt][3]));
    }
    mx0 = fmaxf(mx0, __shfl_xor_sync(0xffffffff, mx0, 1));
    mx0 = fmaxf(mx0, __shfl_xor_sync(0xffffffff, mx0, 2));
    mx1 = fmaxf(mx1, __shfl_xor_sync(0xffffffff, mx1, 1));
    mx1 = fmaxf(mx1, __shfl_xor_sync(0xffffffff, mx1, 2));
    float s0 = 0.f, s1 = 0.f;
    #pragma unroll
    for (int nt = 0; nt < 8; nt++) {
        sc[nt][0] = __expf((sc[nt][0] - mx0) * SCALE_);
        sc[nt][1] = __expf((sc[nt][1] - mx0) * SCALE_);
        sc[nt][2] = __expf((sc[nt][2] - mx1) * SCALE_);
        sc[nt][3] = __expf((sc[nt][3] - mx1) * SCALE_);
        s0 += sc[nt][0] + sc[nt][1];
        s1 += sc[nt][2] + sc[nt][3];
    }
    s0 += __shfl_xor_sync(0xffffffff, s0, 1);
    s0 += __shfl_xor_sync(0xffffffff, s0, 2);
    s1 += __shfl_xor_sync(0xffffffff, s1, 1);
    s1 += __shfl_xor_sync(0xffffffff, s1, 2);
    const float i0 = 1.f / s0, i1 = 1.f / s1;

    // convert to bf16 A-fragments (C-frag of tile nt -> A-frag halves)
    uint32_t pa[8][2];
    #pragma unroll
    for (int nt = 0; nt < 8; nt++) {
        pa[nt][0] = pack_bf16(sc[nt][0] * i0, sc[nt][1] * i0);
        pa[nt][1] = pack_bf16(sc[nt][2] * i1, sc[nt][3] * i1);
    }

    // out = attn @ V
    float oc[8][4];
    #pragma unroll
    for (int nt = 0; nt < 8; nt++) { oc[nt][0]=0.f; oc[nt][1]=0.f; oc[nt][2]=0.f; oc[nt][3]=0.f; }
    #pragma unroll
    for (int ks = 0; ks < 4; ks++) {
        uint32_t a0 = pa[2 * ks][0], a1 = pa[2 * ks][1];
        uint32_t a2 = pa[2 * ks + 1][0], a3 = pa[2 * ks + 1][1];
        const int kcol = ks * 16 + 2 * tg;
        #pragma unroll
        for (int nt = 0; nt < 8; nt++) {
            uint32_t b0 = *reinterpret_cast<const uint32_t*>(Vt + (nt * 8 + g) * 72 + kcol);
            uint32_t b1 = *reinterpret_cast<const uint32_t*>(Vt + (nt * 8 + g) * 72 + kcol + 8);
            mma16816(oc[nt], a0, a1, a2, a3, b0, b1);
        }
    }
    // store to g_o [n][t][h*64+d]
    #pragma unroll
    for (int nt = 0; nt < 8; nt++) {
        int dcol = nt * 8 + 2 * tg;
        *reinterpret_cast<uint32_t*>(g_o + base + r0 * HD_ + dcol)       = pack_bf16(oc[nt][0], oc[nt][1]);
        *reinterpret_cast<uint32_t*>(g_o + base + (r0 + 8) * HD_ + dcol) = pack_bf16(oc[nt][2], oc[nt][3]);
    }
}

// ---------------- K3: output projection + bias + residual (inverse roll scatter) ----------------
// grid: (4, 512). block 256 threads, tile 64 rows x 128 cols, K = 512
__global__ __launch_bounds__(256) void proj_kernel(const float* __restrict__ x,
                                                   const float* __restrict__ bo,
                                                   float* __restrict__ out) {
    __shared__ __nv_bfloat16 As[64 * 72];
    __shared__ __nv_bfloat16 Bs[128 * 72];

    const int n = blockIdx.y;
    const int colbase = blockIdx.x * 128;
    const int tid = threadIdx.x, lane = tid & 31, warp = tid >> 5;
    const int g = lane >> 2, tg = lane & 3;
    const int wm = warp >> 1, wn = warp & 1;

    const int b  = n >> 6;
    const int wh = (n >> 3) & 7;
    const int ww = n & 7;

    float acc[8][4];
    #pragma unroll
    for (int nt = 0; nt < 8; nt++) { acc[nt][0]=0.f; acc[nt][1]=0.f; acc[nt][2]=0.f; acc[nt][3]=0.f; }

    const int abase = n * T_ * HD_;
    for (int kc = 0; kc < 8; kc++) {
        if (kc) __syncthreads();
        // A: 64 rows x 64 bf16 from g_o
        #pragma unroll
        for (int e = 0; e < 2; e++) {
            int it = tid + e * 256;   // 0..511
            int row = it >> 3, seg = it & 7;
            *reinterpret_cast<uint4*>(As + row * 72 + seg * 8) =
                *reinterpret_cast<const uint4*>(g_o + abase + row * HD_ + kc * 64 + seg * 8);
        }
        // B: 128 out-channels x 64 k from g_woT [c][hd]
        #pragma unroll
        for (int e = 0; e < 4; e++) {
            int it = tid + e * 256;
            int rn = it >> 3, seg = it & 7;
            *reinterpret_cast<uint4*>(Bs + rn * 72 + seg * 8) =
                *reinterpret_cast<const uint4*>(g_woT + (colbase + rn) * HD_ + kc * 64 + seg * 8);
        }
        __syncthreads();
        #pragma unroll
        for (int ks = 0; ks < 4; ks++) {
            const int ar0 = wm * 16 + g;
            const int kcol = ks * 16 + 2 * tg;
            uint32_t a0 = *reinterpret_cast<const uint32_t*>(As + ar0 * 72 + kcol);
            uint32_t a1 = *reinterpret_cast<const uint32_t*>(As + (ar0 + 8) * 72 + kcol);
            uint32_t a2 = *reinterpret_cast<const uint32_t*>(As + ar0 * 72 + kcol + 8);
            uint32_t a3 = *reinterpret_cast<const uint32_t*>(As + (ar0 + 8) * 72 + kcol + 8);
            #pragma unroll
            for (int nt = 0; nt < 8; nt++) {
                int bn = wn * 64 + nt * 8 + g;
                uint32_t b0 = *reinterpret_cast<const uint32_t*>(Bs + bn * 72 + kcol);
                uint32_t b1 = *reinterpret_cast<const uint32_t*>(Bs + bn * 72 + kcol + 8);
                mma16816(acc[nt], a0, a1, a2, a3, b0, b1);
            }
        }
    }

    // epilogue: scatter with inverse roll, add bias + residual, fp32 out
    const int t0 = wm * 16 + g;       // token rows t0 and t0+8
    #pragma unroll
    for (int half = 0; half < 2; half++) {
        int t = t0 + half * 8;
        int i = t >> 3, j = t & 7;
        int r  = (wh * 8 + i + 4) & 63;
        int cc = (ww * 8 + j + 4) & 63;
        int off = ((b * 64 + r) * 64 + cc) * C_;
        #pragma unroll
        for (int nt = 0; nt < 8; nt++) {
            int col = colbase + wn * 64 + nt * 8 + 2 * tg;
            float2 xr = *reinterpret_cast<const float2*>(x + off + col);
            float2 o;
            o.x = acc[nt][2 * half + 0] + bo[col]     + xr.x;
            o.y = acc[nt][2 * half + 1] + bo[col + 1] + xr.y;
            *reinterpret_cast<float2*>(out + off + col) = o;
        }
    }
}

// ---------------- launch ----------------
extern "C" void kernel_launch(void* const* d_in, const int* in_sizes, int n_in,
                              void* d_out, int out_size) {
    const float* x  = (const float*)d_in[0];
    const float* wq = (const float*)d_in[1];
    const float* bq = (const float*)d_in[2];
    const float* wk = (const float*)d_in[3];
    const float* bk = (const float*)d_in[4];
    const float* wv = (const float*)d_in[5];
    const float* bv = (const float*)d_in[6];
    const float* wo = (const float*)d_in[7];
    const float* bo = (const float*)d_in[8];
    float* out = (float*)d_out;

    convert_weights<<<(C_ * HD_ + 255) / 256, 256>>>(wq, wk, wv, wo);
    dim3 g1(12, NWIN);
    qkv_kernel<<<g1, 256>>>(x, bq, bk, bv);
    attn_kernel<<<NWIN * NH_, 128>>>();
    dim3 g3(4, NWIN);
    proj_kernel<<<g3, 256>>>(x, bo, out);
}

// round 2
// speedup vs baseline: 1.4249x; 1.4249x over previous
#include <cuda_runtime.h>
#include <cuda_bf16.h>
#include <stdint.h>

#define NWIN   512
#define T_     64
#define C_     512
#define NH_    8
#define D_     64
#define MROWS  32768        // NWIN * T_
#define N_QKV  1536
#define SCALE_ 0.125f

// ---------------- scratch ----------------
__device__ __nv_bfloat16 g_xw [MROWS * C_];      // gathered+rolled x, bf16
__device__ __nv_bfloat16 g_qkv[MROWS * N_QKV];   // Q|K|V concat
__device__ __nv_bfloat16 g_o  [MROWS * C_];      // attention out
__device__ __nv_bfloat16 g_wT [N_QKV * C_];      // [out col][k]
__device__ __nv_bfloat16 g_woT[C_ * C_];         // [out c][k=hd]

// ---------------- asm helpers ----------------
__device__ __forceinline__ void mma16816(float* c, uint32_t a0, uint32_t a1, uint32_t a2, uint32_t a3,
                                         uint32_t b0, uint32_t b1) {
    asm volatile(
        "mma.sync.aligned.m16n8k16.row.col.f32.bf16.bf16.f32 "
        "{%0,%1,%2,%3}, {%4,%5,%6,%7}, {%8,%9}, {%0,%1,%2,%3};"
        : "+f"(c[0]), "+f"(c[1]), "+f"(c[2]), "+f"(c[3])
        : "r"(a0), "r"(a1), "r"(a2), "r"(a3), "r"(b0), "r"(b1));
}
__device__ __forceinline__ void ldsm4(uint32_t* r, uint32_t addr) {
    asm volatile("ldmatrix.sync.aligned.m8n8.x4.shared.b16 {%0,%1,%2,%3}, [%4];"
                 : "=r"(r[0]), "=r"(r[1]), "=r"(r[2]), "=r"(r[3]) : "r"(addr));
}
__device__ __forceinline__ void ldsm4t(uint32_t* r, uint32_t addr) {
    asm volatile("ldmatrix.sync.aligned.m8n8.x4.trans.shared.b16 {%0,%1,%2,%3}, [%4];"
                 : "=r"(r[0]), "=r"(r[1]), "=r"(r[2]), "=r"(r[3]) : "r"(addr));
}
__device__ __forceinline__ void cp16(uint32_t smem_dst, const void* gmem_src) {
    asm volatile("cp.async.cg.shared.global [%0], [%1], 16;" :: "r"(smem_dst), "l"(gmem_src));
}
__device__ __forceinline__ void cp_commit() { asm volatile("cp.async.commit_group;"); }
template<int N> __device__ __forceinline__ void cp_wait() { asm volatile("cp.async.wait_group %0;" :: "n"(N)); }
__device__ __forceinline__ uint32_t smem_u32(const void* p) {
    return (uint32_t)__cvta_generic_to_shared(p);
}
__device__ __forceinline__ uint32_t pack_bf16(float a, float b) {
    __nv_bfloat162 t = __floats2bfloat162_rn(a, b);
    return *reinterpret_cast<uint32_t*>(&t);
}

// ---------------- K0: weight convert + transpose ----------------
__global__ void convert_weights(const float* __restrict__ wq, const float* __restrict__ wk,
                                const float* __restrict__ wv, const float* __restrict__ wo) {
    int idx = blockIdx.x * blockDim.x + threadIdx.x;   // 0..262143
    if (idx >= C_ * C_) return;
    int r = idx >> 9;      // source row (c for wq/wk/wv; hd for wo)
    int j = idx & 511;     // source col (hd for wq/wk/wv; c for wo)
    g_wT[j * C_ + r]          = __float2bfloat16(wq[idx]);
    g_wT[(512 + j) * C_ + r]  = __float2bfloat16(wk[idx]);
    g_wT[(1024 + j) * C_ + r] = __float2bfloat16(wv[idx]);
    g_woT[j * C_ + r]         = __float2bfloat16(wo[idx]);
}

// ---------------- K0b: gather (window partition + roll) fp32 -> bf16 ----------------
__global__ __launch_bounds__(256) void gather_kernel(const float* __restrict__ x) {
    int idx = blockIdx.x * 256 + threadIdx.x;    // 0 .. 4194303
    int row = idx >> 7;                           // 128 float4-chunks per row
    int ch  = idx & 127;
    int win = row >> 6, t = row & 63;
    int b = win >> 6, wh = (win >> 3) & 7, ww = win & 7;
    int i = t >> 3, j = t & 7;
    int r  = (wh * 8 + i + 4) & 63;
    int cc = (ww * 8 + j + 4) & 63;
    float4 f = *reinterpret_cast<const float4*>(x + (((b * 64 + r) * 64 + cc) << 9) + ch * 4);
    uint2 o;
    o.x = pack_bf16(f.x, f.y);
    o.y = pack_bf16(f.z, f.w);
    *reinterpret_cast<uint2*>(g_xw + row * C_ + ch * 4) = o;
}

// ---------------- GEMM constants ----------------
// BM=128, BN=128, BK=32, 2 stages. smem tile stride = 40 bf16 (80B rows, ldsm conflict-free)
#define BK_     32
#define TSTR_   40
#define TILE_E  (128 * TSTR_)          // elements per tile
#define STAGE_E (2 * TILE_E)           // A + B per stage

// ---------------- K1: QKV GEMM  [32768,512] x [512,1536] ----------------
__global__ __launch_bounds__(256, 2) void qkv_kernel(const float* __restrict__ bq,
                                                     const float* __restrict__ bk,
                                                     const float* __restrict__ bv) {
    __shared__ __nv_bfloat16 sm[2 * STAGE_E];
    const int tid = threadIdx.x, lane = tid & 31, warp = tid >> 5;
    const int g = lane >> 2, tg = lane & 3;
    const int wm = warp >> 1, wn = warp & 1;
    const int mbase = blockIdx.y * 128, nbase = blockIdx.x * 128;

    const __nv_bfloat16* Ag = g_xw + (size_t)mbase * C_;
    const __nv_bfloat16* Bg = g_wT + (size_t)nbase * C_;
    const uint32_t smb = smem_u32(sm);

    // per-thread copy coords: 512 chunks per tile, 2 per thread
    const int r0c = tid >> 2, s0c = tid & 3;          // chunk tid
    const int r1c = (tid + 256) >> 2, s1c = tid & 3;  // chunk tid+256

    // smem read base addrs (bytes)
    const uint32_t aBase = smb + (((wm * 32 + (lane & 15)) * TSTR_ + ((lane >> 4) << 3)) << 1);
    const uint32_t bBase = smb + ((TILE_E + ((wn * 64 + ((lane >> 4) & 1) * 8 + (lane & 7)) * TSTR_)
                                   + (((lane >> 3) & 1) << 3)) << 1);

    float acc[2][8][4];
    #pragma unroll
    for (int mi = 0; mi < 2; mi++)
        #pragma unroll
        for (int nt = 0; nt < 8; nt++)
            #pragma unroll
            for (int e = 0; e < 4; e++) acc[mi][nt][e] = 0.f;

    // prologue: stage 0, chunk 0
    {
        uint32_t dA = smb, dB = smb + (TILE_E << 1);
        cp16(dA + ((r0c * TSTR_ + s0c * 8) << 1), Ag + r0c * C_ + s0c * 8);
        cp16(dA + ((r1c * TSTR_ + s1c * 8) << 1), Ag + r1c * C_ + s1c * 8);
        cp16(dB + ((r0c * TSTR_ + s0c * 8) << 1), Bg + r0c * C_ + s0c * 8);
        cp16(dB + ((r1c * TSTR_ + s1c * 8) << 1), Bg + r1c * C_ + s1c * 8);
        cp_commit();
    }

    for (int kc = 0; kc < 16; kc++) {
        if (kc < 15) {
            int st = (kc + 1) & 1, ko = (kc + 1) * BK_;
            uint32_t dA = smb + st * (STAGE_E << 1), dB = dA + (TILE_E << 1);
            cp16(dA + ((r0c * TSTR_ + s0c * 8) << 1), Ag + r0c * C_ + ko + s0c * 8);
            cp16(dA + ((r1c * TSTR_ + s1c * 8) << 1), Ag + r1c * C_ + ko + s1c * 8);
            cp16(dB + ((r0c * TSTR_ + s0c * 8) << 1), Bg + r0c * C_ + ko + s0c * 8);
            cp16(dB + ((r1c * TSTR_ + s1c * 8) << 1), Bg + r1c * C_ + ko + s1c * 8);
            cp_commit();
            cp_wait<1>();
        } else {
            cp_wait<0>();
        }
        __syncthreads();
        const uint32_t stoff = (kc & 1) * (STAGE_E << 1);
        #pragma unroll
        for (int ks = 0; ks < 2; ks++) {
            uint32_t a[2][4], bb[4][4];
            #pragma unroll
            for (int mi = 0; mi < 2; mi++)
                ldsm4(a[mi], aBase + stoff + (((mi * 16) * TSTR_ + ks * 16) << 1));
            #pragma unroll
            for (int p = 0; p < 4; p++)
                ldsm4(bb[p], bBase + stoff + (((p * 16) * TSTR_ + ks * 16) << 1));
            #pragma unroll
            for (int mi = 0; mi < 2; mi++)
                #pragma unroll
                for (int nt = 0; nt < 8; nt++)
                    mma16816(acc[mi][nt], a[mi][0], a[mi][1], a[mi][2], a[mi][3],
                             bb[nt >> 1][(nt & 1) * 2], bb[nt >> 1][(nt & 1) * 2 + 1]);
        }
        __syncthreads();
    }

    // epilogue: +bias, bf16 store to g_qkv
    #pragma unroll
    for (int mi = 0; mi < 2; mi++) {
        int row = mbase + wm * 32 + mi * 16 + g;
        #pragma unroll
        for (int nt = 0; nt < 8; nt++) {
            int col = nbase + wn * 64 + nt * 8 + 2 * tg;
            int sel = col >> 9, ci = col & 511;
            const float* bias = (sel == 0) ? bq : (sel == 1) ? bk : bv;
            float b0f = bias[ci], b1f = bias[ci + 1];
            *reinterpret_cast<uint32_t*>(g_qkv + (size_t)row * N_QKV + col) =
                pack_bf16(acc[mi][nt][0] + b0f, acc[mi][nt][1] + b1f);
            *reinterpret_cast<uint32_t*>(g_qkv + (size_t)(row + 8) * N_QKV + col) =
                pack_bf16(acc[mi][nt][2] + b0f, acc[mi][nt][3] + b1f);
        }
    }
}

// ---------------- K2: attention per (window, head) ----------------
__global__ __launch_bounds__(128) void attn_kernel() {
    __shared__ __nv_bfloat16 Qs[64 * 72];
    __shared__ __nv_bfloat16 Ks[64 * 72];
    __shared__ __nv_bfloat16 Vs[64 * 72];   // [token k][d]

    const int nh = blockIdx.x;
    const int n = nh >> 3, h = nh & 7;
    const int tid = threadIdx.x, lane = tid & 31, warp = tid >> 5;
    const int g = lane >> 2, tg = lane & 3;

    const __nv_bfloat16* src = g_qkv + (size_t)(n * 64) * N_QKV + h * 64;
    #pragma unroll
    for (int e = 0; e < 4; e++) {
        int it = tid + e * 128;
        int row = it >> 3, seg = it & 7;
        *reinterpret_cast<uint4*>(Qs + row * 72 + seg * 8) =
            *reinterpret_cast<const uint4*>(src + (size_t)row * N_QKV + seg * 8);
        *reinterpret_cast<uint4*>(Ks + row * 72 + seg * 8) =
            *reinterpret_cast<const uint4*>(src + (size_t)row * N_QKV + 512 + seg * 8);
        *reinterpret_cast<uint4*>(Vs + row * 72 + seg * 8) =
            *reinterpret_cast<const uint4*>(src + (size_t)row * N_QKV + 1024 + seg * 8);
    }
    __syncthreads();

    const uint32_t qB = smem_u32(Qs) + (((warp * 16 + (lane & 15)) * 72 + ((lane >> 4) << 3)) << 1);
    const uint32_t kB = smem_u32(Ks) + (((((lane >> 4) & 1) * 8 + (lane & 7)) * 72 + (((lane >> 3) & 1) << 3)) << 1);
    const uint32_t vB = smem_u32(Vs) + ((((lane & 7) + ((lane >> 3) & 1) * 8) * 72 + ((lane >> 4) & 1) * 8) << 1);

    // scores = Q K^T
    float sc[8][4];
    #pragma unroll
    for (int nt = 0; nt < 8; nt++) { sc[nt][0]=0.f; sc[nt][1]=0.f; sc[nt][2]=0.f; sc[nt][3]=0.f; }
    #pragma unroll
    for (int ks = 0; ks < 4; ks++) {
        uint32_t a[4], bb[4][4];
        ldsm4(a, qB + ((ks * 16) << 1));
        #pragma unroll
        for (int p = 0; p < 4; p++)
            ldsm4(bb[p], kB + (((p * 16) * 72 + ks * 16) << 1));
        #pragma unroll
        for (int nt = 0; nt < 8; nt++)
            mma16816(sc[nt], a[0], a[1], a[2], a[3],
                     bb[nt >> 1][(nt & 1) * 2], bb[nt >> 1][(nt & 1) * 2 + 1]);
    }

    // softmax over 64 keys
    float mx0 = -1e30f, mx1 = -1e30f;
    #pragma unroll
    for (int nt = 0; nt < 8; nt++) {
        mx0 = fmaxf(mx0, fmaxf(sc[nt][0], sc[nt][1]));
        mx1 = fmaxf(mx1, fmaxf(sc[nt][2], sc[nt][3]));
    }
    mx0 = fmaxf(mx0, __shfl_xor_sync(0xffffffff, mx0, 1));
    mx0 = fmaxf(mx0, __shfl_xor_sync(0xffffffff, mx0, 2));
    mx1 = fmaxf(mx1, __shfl_xor_sync(0xffffffff, mx1, 1));
    mx1 = fmaxf(mx1, __shfl_xor_sync(0xffffffff, mx1, 2));
    float s0 = 0.f, s1 = 0.f;
    #pragma unroll
    for (int nt = 0; nt < 8; nt++) {
        sc[nt][0] = __expf((sc[nt][0] - mx0) * SCALE_);
        sc[nt][1] = __expf((sc[nt][1] - mx0) * SCALE_);
        sc[nt][2] = __expf((sc[nt][2] - mx1) * SCALE_);
        sc[nt][3] = __expf((sc[nt][3] - mx1) * SCALE_);
        s0 += sc[nt][0] + sc[nt][1];
        s1 += sc[nt][2] + sc[nt][3];
    }
    s0 += __shfl_xor_sync(0xffffffff, s0, 1);
    s0 += __shfl_xor_sync(0xffffffff, s0, 2);
    s1 += __shfl_xor_sync(0xffffffff, s1, 1);
    s1 += __shfl_xor_sync(0xffffffff, s1, 2);
    const float i0 = 1.f / s0, i1 = 1.f / s1;

    uint32_t pa[8][2];
    #pragma unroll
    for (int nt = 0; nt < 8; nt++) {
        pa[nt][0] = pack_bf16(sc[nt][0] * i0, sc[nt][1] * i0);
        pa[nt][1] = pack_bf16(sc[nt][2] * i1, sc[nt][3] * i1);
    }

    // out = P @ V  (V fragments via ldmatrix.trans)
    float oc[8][4];
    #pragma unroll
    for (int nt = 0; nt < 8; nt++) { oc[nt][0]=0.f; oc[nt][1]=0.f; oc[nt][2]=0.f; oc[nt][3]=0.f; }
    #pragma unroll
    for (int ks = 0; ks < 4; ks++) {
        uint32_t bb[4][4];
        #pragma unroll
        for (int p = 0; p < 4; p++)
            ldsm4t(bb[p], vB + (((ks * 16) * 72 + p * 16) << 1));
        uint32_t a0 = pa[2 * ks][0], a1 = pa[2 * ks][1];
        uint32_t a2 = pa[2 * ks + 1][0], a3 = pa[2 * ks + 1][1];
        #pragma unroll
        for (int nt = 0; nt < 8; nt++)
            mma16816(oc[nt], a0, a1, a2, a3,
                     bb[nt >> 1][(nt & 1) * 2], bb[nt >> 1][(nt & 1) * 2 + 1]);
    }

    const int r0 = warp * 16 + g;
    __nv_bfloat16* dst = g_o + (size_t)(n * 64) * C_ + h * 64;
    #pragma unroll
    for (int nt = 0; nt < 8; nt++) {
        int dcol = nt * 8 + 2 * tg;
        *reinterpret_cast<uint32_t*>(dst + (size_t)r0 * C_ + dcol)       = pack_bf16(oc[nt][0], oc[nt][1]);
        *reinterpret_cast<uint32_t*>(dst + (size_t)(r0 + 8) * C_ + dcol) = pack_bf16(oc[nt][2], oc[nt][3]);
    }
}

// ---------------- K3: output projection + bias + residual (inverse roll scatter) ----------------
__global__ __launch_bounds__(256, 2) void proj_kernel(const float* __restrict__ x,
                                                      const float* __restrict__ bo,
                                                      float* __restrict__ out) {
    __shared__ __nv_bfloat16 sm[2 * STAGE_E];
    const int tid = threadIdx.x, lane = tid & 31, warp = tid >> 5;
    const int g = lane >> 2, tg = lane & 3;
    const int wm = warp >> 1, wn = warp & 1;
    const int mbase = blockIdx.y * 128, nbase = blockIdx.x * 128;

    const __nv_bfloat16* Ag = g_o + (size_t)mbase * C_;
    const __nv_bfloat16* Bg = g_woT + (size_t)nbase * C_;
    const uint32_t smb = smem_u32(sm);

    const int r0c = tid >> 2, s0c = tid & 3;
    const int r1c = (tid + 256) >> 2, s1c = tid & 3;

    const uint32_t aBase = smb + (((wm * 32 + (lane & 15)) * TSTR_ + ((lane >> 4) << 3)) << 1);
    const uint32_t bBase = smb + ((TILE_E + ((wn * 64 + ((lane >> 4) & 1) * 8 + (lane & 7)) * TSTR_)
                                   + (((lane >> 3) & 1) << 3)) << 1);

    float acc[2][8][4];
    #pragma unroll
    for (int mi = 0; mi < 2; mi++)
        #pragma unroll
        for (int nt = 0; nt < 8; nt++)
            #pragma unroll
            for (int e = 0; e < 4; e++) acc[mi][nt][e] = 0.f;

    {
        uint32_t dA = smb, dB = smb + (TILE_E << 1);
        cp16(dA + ((r0c * TSTR_ + s0c * 8) << 1), Ag + r0c * C_ + s0c * 8);
        cp16(dA + ((r1c * TSTR_ + s1c * 8) << 1), Ag + r1c * C_ + s1c * 8);
        cp16(dB + ((r0c * TSTR_ + s0c * 8) << 1), Bg + r0c * C_ + s0c * 8);
        cp16(dB + ((r1c * TSTR_ + s1c * 8) << 1), Bg + r1c * C_ + s1c * 8);
        cp_commit();
    }

    for (int kc = 0; kc < 16; kc++) {
        if (kc < 15) {
            int st = (kc + 1) & 1, ko = (kc + 1) * BK_;
            uint32_t dA = smb + st * (STAGE_E << 1), dB = dA + (TILE_E << 1);
            cp16(dA + ((r0c * TSTR_ + s0c * 8) << 1), Ag + r0c * C_ + ko + s0c * 8);
            cp16(dA + ((r1c * TSTR_ + s1c * 8) << 1), Ag + r1c * C_ + ko + s1c * 8);
            cp16(dB + ((r0c * TSTR_ + s0c * 8) << 1), Bg + r0c * C_ + ko + s0c * 8);
            cp16(dB + ((r1c * TSTR_ + s1c * 8) << 1), Bg + r1c * C_ + ko + s1c * 8);
            cp_commit();
            cp_wait<1>();
        } else {
            cp_wait<0>();
        }
        __syncthreads();
        const uint32_t stoff = (kc & 1) * (STAGE_E << 1);
        #pragma unroll
        for (int ks = 0; ks < 2; ks++) {
            uint32_t a[2][4], bb[4][4];
            #pragma unroll
            for (int mi = 0; mi < 2; mi++)
                ldsm4(a[mi], aBase + stoff + (((mi * 16) * TSTR_ + ks * 16) << 1));
            #pragma unroll
            for (int p = 0; p < 4; p++)
                ldsm4(bb[p], bBase + stoff + (((p * 16) * TSTR_ + ks * 16) << 1));
            #pragma unroll
            for (int mi = 0; mi < 2; mi++)
                #pragma unroll
                for (int nt = 0; nt < 8; nt++)
                    mma16816(acc[mi][nt], a[mi][0], a[mi][1], a[mi][2], a[mi][3],
                             bb[nt >> 1][(nt & 1) * 2], bb[nt >> 1][(nt & 1) * 2 + 1]);
        }
        __syncthreads();
    }

    // epilogue: scatter (inverse roll) + bias + residual
    #pragma unroll
    for (int mi = 0; mi < 2; mi++) {
        #pragma unroll
        for (int half = 0; half < 2; half++) {
            int row = mbase + wm * 32 + mi * 16 + g + half * 8;
            int win = row >> 6, t = row & 63;
            int b = win >> 6, wh = (win >> 3) & 7, ww = win & 7;
            int i = t >> 3, j = t & 7;
            int r  = (wh * 8 + i + 4) & 63;
            int cc = (ww * 8 + j + 4) & 63;
            size_t off = (size_t)((b * 64 + r) * 64 + cc) * C_;
            #pragma unroll
            for (int nt = 0; nt < 8; nt++) {
                int col = nbase + wn * 64 + nt * 8 + 2 * tg;
                float2 xr = *reinterpret_cast<const float2*>(x + off + col);
                float2 o;
                o.x = acc[mi][nt][2 * half + 0] + bo[col]     + xr.x;
                o.y = acc[mi][nt][2 * half + 1] + bo[col + 1] + xr.y;
                *reinterpret_cast<float2*>(out + off + col) = o;
            }
        }
    }
}

// ---------------- launch ----------------
extern "C" void kernel_launch(void* const* d_in, const int* in_sizes, int n_in,
                              void* d_out, int out_size) {
    const float* x  = (const float*)d_in[0];
    const float* wq = (const float*)d_in[1];
    const float* bq = (const float*)d_in[2];
    const float* wk = (const float*)d_in[3];
    const float* bk = (const float*)d_in[4];
    const float* wv = (const float*)d_in[5];
    const float* bv = (const float*)d_in[6];
    const float* wo = (const float*)d_in[7];
    const float* bo = (const float*)d_in[8];
    float* out = (float*)d_out;

    convert_weights<<<(C_ * C_ + 255) / 256, 256>>>(wq, wk, wv, wo);
    gather_kernel<<<(MROWS * C_ / 4) / 256, 256>>>(x);
    dim3 g1(12, 256);
    qkv_kernel<<<g1, 256>>>(bq, bk, bv);
    attn_kernel<<<NWIN * NH_, 128>>>();
    dim3 g3(4, 256);
    proj_kernel<<<g3, 256>>>(x, bo, out);
}

// round 4
// speedup vs baseline: 1.5037x; 1.0553x over previous
#include <cuda_runtime.h>
#include <cuda_bf16.h>
#include <stdint.h>

#define NWIN   512
#define T_     64
#define C_     512
#define NH_    8
#define D_     64
#define MROWS  32768        // NWIN * T_
#define N_QKV  1536
#define SCALE_ 0.125f

// ---------------- scratch ----------------
__device__ __nv_bfloat16 g_xw [MROWS * C_];      // gathered+rolled x, bf16
__device__ __nv_bfloat16 g_qkv[MROWS * N_QKV];   // Q|K|V concat
__device__ __nv_bfloat16 g_o  [MROWS * C_];      // attention out
__device__ __nv_bfloat16 g_wT [N_QKV * C_];      // [out col][k]
__device__ __nv_bfloat16 g_woT[C_ * C_];         // [out c][k=hd]

// ---------------- asm helpers ----------------
__device__ __forceinline__ void mma16816(float* c, uint32_t a0, uint32_t a1, uint32_t a2, uint32_t a3,
                                         uint32_t b0, uint32_t b1) {
    asm volatile(
        "mma.sync.aligned.m16n8k16.row.col.f32.bf16.bf16.f32 "
        "{%0,%1,%2,%3}, {%4,%5,%6,%7}, {%8,%9}, {%0,%1,%2,%3};"
        : "+f"(c[0]), "+f"(c[1]), "+f"(c[2]), "+f"(c[3])
        : "r"(a0), "r"(a1), "r"(a2), "r"(a3), "r"(b0), "r"(b1));
}
__device__ __forceinline__ void ldsm4(uint32_t* r, uint32_t addr) {
    asm volatile("ldmatrix.sync.aligned.m8n8.x4.shared.b16 {%0,%1,%2,%3}, [%4];"
                 : "=r"(r[0]), "=r"(r[1]), "=r"(r[2]), "=r"(r[3]) : "r"(addr));
}
__device__ __forceinline__ void ldsm4t(uint32_t* r, uint32_t addr) {
    asm volatile("ldmatrix.sync.aligned.m8n8.x4.trans.shared.b16 {%0,%1,%2,%3}, [%4];"
                 : "=r"(r[0]), "=r"(r[1]), "=r"(r[2]), "=r"(r[3]) : "r"(addr));
}
__device__ __forceinline__ void cp16(uint32_t smem_dst, const void* gmem_src) {
    asm volatile("cp.async.cg.shared.global [%0], [%1], 16;" :: "r"(smem_dst), "l"(gmem_src));
}
__device__ __forceinline__ void cp_commit() { asm volatile("cp.async.commit_group;"); }
template<int N> __device__ __forceinline__ void cp_wait() { asm volatile("cp.async.wait_group %0;" :: "n"(N)); }
__device__ __forceinline__ uint32_t smem_u32(const void* p) {
    return (uint32_t)__cvta_generic_to_shared(p);
}
__device__ __forceinline__ uint32_t pack_bf16(float a, float b) {
    __nv_bfloat162 t = __floats2bfloat162_rn(a, b);
    return *reinterpret_cast<uint32_t*>(&t);
}

// ---------------- K0: weight convert + transpose ----------------
__global__ void convert_weights(const float* __restrict__ wq, const float* __restrict__ wk,
                                const float* __restrict__ wv, const float* __restrict__ wo) {
    int idx = blockIdx.x * blockDim.x + threadIdx.x;
    if (idx >= C_ * C_) return;
    int r = idx >> 9;
    int j = idx & 511;
    g_wT[j * C_ + r]          = __float2bfloat16(wq[idx]);
    g_wT[(512 + j) * C_ + r]  = __float2bfloat16(wk[idx]);
    g_wT[(1024 + j) * C_ + r] = __float2bfloat16(wv[idx]);
    g_woT[j * C_ + r]         = __float2bfloat16(wo[idx]);
}

// ---------------- K0b: gather (window partition + roll) fp32 -> bf16 ----------------
__global__ __launch_bounds__(256) void gather_kernel(const float* __restrict__ x) {
    int idx = blockIdx.x * 256 + threadIdx.x;
    int row = idx >> 7;
    int ch  = idx & 127;
    int win = row >> 6, t = row & 63;
    int b = win >> 6, wh = (win >> 3) & 7, ww = win & 7;
    int i = t >> 3, j = t & 7;
    int r  = (wh * 8 + i + 4) & 63;
    int cc = (ww * 8 + j + 4) & 63;
    float4 f = *reinterpret_cast<const float4*>(x + (((b * 64 + r) * 64 + cc) << 9) + ch * 4);
    uint2 o;
    o.x = pack_bf16(f.x, f.y);
    o.y = pack_bf16(f.z, f.w);
    *reinterpret_cast<uint2*>(g_xw + row * C_ + ch * 4) = o;
}

// ---------------- GEMM config: BM=128, BN=128, BK=32, S=3 stages ----------------
#define BK_        32
#define TSTR_      40                       // bf16 elems per smem row (80B, ldsm conflict-free)
#define ROW_B      (TSTR_ * 2)              // 80 bytes per row
#define STAGE_BYTES (256 * ROW_B)           // A(128 rows)+B(128 rows) = 20480 B
#define S_         3
#define SMEM_DYN   (S_ * STAGE_BYTES)       // 61440 B

// load one BK=32 chunk of A[128xBK] + B[128xBK] into stage `st`
// 1024 cp16 total (4 per thread). combined row: 0..127 A, 128..255 B.
__device__ __forceinline__ void load_chunk(uint32_t dsm, int st,
                                           const __nv_bfloat16* Ag,
                                           const __nv_bfloat16* Bg,
                                           int ko, int tid) {
    const uint32_t base = dsm + st * STAGE_BYTES;
    #pragma unroll
    for (int i = 0; i < 4; i++) {
        int idx = tid + i * 256;          // 0..1023
        int row = idx >> 2, chunk = idx & 3;
        const __nv_bfloat16* src = (row < 128)
            ? (Ag + (size_t)row * C_ + ko + chunk * 8)
            : (Bg + (size_t)(row - 128) * C_ + ko + chunk * 8);
        cp16(base + row * ROW_B + chunk * 16, src);
    }
}

// mainloop: 16 chunks, 3-stage pipeline, ONE barrier per chunk.
// acc[2][8][4] per thread (warp tile 32x64, 8 warps in 4x2 arrangement)
__device__ __forceinline__ void gemm_mainloop(uint32_t dsm,
                                              const __nv_bfloat16* Ag,
                                              const __nv_bfloat16* Bg,
                                              float acc[2][8][4]) {
    const int tid = threadIdx.x, lane = tid & 31, warp = tid >> 5;
    const int wm = warp >> 1, wn = warp & 1;

    // smem read bases (bytes). A rows [0,128), B rows [128,256) of each stage.
    const uint32_t aBase = dsm + (wm * 32 + (lane & 15)) * ROW_B + ((lane >> 4) << 4);
    const uint32_t bBase = dsm + 128 * ROW_B
                         + (wn * 64 + ((lane >> 4) & 1) * 8 + (lane & 7)) * ROW_B
                         + (((lane >> 3) & 1) << 4);

    // prologue: chunks 0,1 -> stages 0,1
    load_chunk(dsm, 0, Ag, Bg, 0, tid);
    cp_commit();
    load_chunk(dsm, 1, Ag, Bg, BK_, tid);
    cp_commit();

    int s = 0;                // stage of chunk kc
    int sl = 2;               // stage for chunk kc+2
    for (int kc = 0; kc < 16; kc++) {
        cp_wait<1>();
        __syncthreads();
        if (kc < 14) load_chunk(dsm, sl, Ag, Bg, (kc + 2) * BK_, tid);
        cp_commit();

        const uint32_t stoff = s * STAGE_BYTES;
        #pragma unroll
        for (int ks = 0; ks < 2; ks++) {
            uint32_t a[2][4], bb[4][4];
            #pragma unroll
            for (int mi = 0; mi < 2; mi++)
                ldsm4(a[mi], aBase + stoff + (mi * 16) * ROW_B + ks * 32);
            #pragma unroll
            for (int p = 0; p < 4; p++)
                ldsm4(bb[p], bBase + stoff + (p * 16) * ROW_B + ks * 32);
            #pragma unroll
            for (int mi = 0; mi < 2; mi++)
                #pragma unroll
                for (int nt = 0; nt < 8; nt++)
                    mma16816(acc[mi][nt], a[mi][0], a[mi][1], a[mi][2], a[mi][3],
                             bb[nt >> 1][(nt & 1) * 2], bb[nt >> 1][(nt & 1) * 2 + 1]);
        }
        s = (s == 2) ? 0 : s + 1;
        sl = (sl == 2) ? 0 : sl + 1;
    }
}

// ---------------- K1: QKV GEMM  [32768,512] x [512,1536] ----------------
__global__ __launch_bounds__(256, 2) void qkv_kernel(const float* __restrict__ bq,
                                                     const float* __restrict__ bk,
                                                     const float* __restrict__ bv) {
    extern __shared__ char dyn[];
    const int tid = threadIdx.x, lane = tid & 31, warp = tid >> 5;
    const int g = lane >> 2, tg = lane & 3;
    const int wm = warp >> 1, wn = warp & 1;
    const int mbase = blockIdx.y * 128, nbase = blockIdx.x * 128;

    const __nv_bfloat16* Ag = g_xw + (size_t)mbase * C_;
    const __nv_bfloat16* Bg = g_wT + (size_t)nbase * C_;

    float acc[2][8][4];
    #pragma unroll
    for (int mi = 0; mi < 2; mi++)
        #pragma unroll
        for (int nt = 0; nt < 8; nt++)
            #pragma unroll
            for (int e = 0; e < 4; e++) acc[mi][nt][e] = 0.f;

    gemm_mainloop(smem_u32(dyn), Ag, Bg, acc);

    #pragma unroll
    for (int mi = 0; mi < 2; mi++) {
        int row = mbase + wm * 32 + mi * 16 + g;
        #pragma unroll
        for (int nt = 0; nt < 8; nt++) {
            int col = nbase + wn * 64 + nt * 8 + 2 * tg;
            int sel = col >> 9, ci = col & 511;
            const float* bias = (sel == 0) ? bq : (sel == 1) ? bk : bv;
            float b0f = bias[ci], b1f = bias[ci + 1];
            *reinterpret_cast<uint32_t*>(g_qkv + (size_t)row * N_QKV + col) =
                pack_bf16(acc[mi][nt][0] + b0f, acc[mi][nt][1] + b1f);
            *reinterpret_cast<uint32_t*>(g_qkv + (size_t)(row + 8) * N_QKV + col) =
                pack_bf16(acc[mi][nt][2] + b0f, acc[mi][nt][3] + b1f);
        }
    }
}

// ---------------- K3: output projection + bias + residual (inverse roll scatter) ----------------
__global__ __launch_bounds__(256, 2) void proj_kernel(const float* __restrict__ x,
                                                      const float* __restrict__ bo,
                                                      float* __restrict__ out) {
    extern __shared__ char dyn[];
    const int tid = threadIdx.x, lane = tid & 31, warp = tid >> 5;
    const int g = lane >> 2, tg = lane & 3;
    const int wm = warp >> 1, wn = warp & 1;
    const int mbase = blockIdx.y * 128, nbase = blockIdx.x * 128;

    const __nv_bfloat16* Ag = g_o + (size_t)mbase * C_;
    const __nv_bfloat16* Bg = g_woT + (size_t)nbase * C_;

    float acc[2][8][4];
    #pragma unroll
    for (int mi = 0; mi < 2; mi++)
        #pragma unroll
        for (int nt = 0; nt < 8; nt++)
            #pragma unroll
            for (int e = 0; e < 4; e++) acc[mi][nt][e] = 0.f;

    gemm_mainloop(smem_u32(dyn), Ag, Bg, acc);

    #pragma unroll
    for (int mi = 0; mi < 2; mi++) {
        #pragma unroll
        for (int half = 0; half < 2; half++) {
            int row = mbase + wm * 32 + mi * 16 + g + half * 8;
            int win = row >> 6, t = row & 63;
            int b = win >> 6, wh = (win >> 3) & 7, ww = win & 7;
            int i = t >> 3, j = t & 7;
            int r  = (wh * 8 + i + 4) & 63;
            int cc = (ww * 8 + j + 4) & 63;
            size_t off = (size_t)((b * 64 + r) * 64 + cc) * C_;
            #pragma unroll
            for (int nt = 0; nt < 8; nt++) {
                int col = nbase + wn * 64 + nt * 8 + 2 * tg;
                float2 xr = *reinterpret_cast<const float2*>(x + off + col);
                float2 o;
                o.x = acc[mi][nt][2 * half + 0] + bo[col]     + xr.x;
                o.y = acc[mi][nt][2 * half + 1] + bo[col + 1] + xr.y;
                *reinterpret_cast<float2*>(out + off + col) = o;
            }
        }
    }
}

// ---------------- K2: attention per (window, head) ----------------
__global__ __launch_bounds__(128) void attn_kernel() {
    __shared__ __nv_bfloat16 Qs[64 * 72];
    __shared__ __nv_bfloat16 Ks[64 * 72];
    __shared__ __nv_bfloat16 Vs[64 * 72];

    const int nh = blockIdx.x;
    const int n = nh >> 3, h = nh & 7;
    const int tid = threadIdx.x, lane = tid & 31, warp = tid >> 5;
    const int g = lane >> 2, tg = lane & 3;

    const __nv_bfloat16* src = g_qkv + (size_t)(n * 64) * N_QKV + h * 64;
    #pragma unroll
    for (int e = 0; e < 4; e++) {
        int it = tid + e * 128;
        int row = it >> 3, seg = it & 7;
        *reinterpret_cast<uint4*>(Qs + row * 72 + seg * 8) =
            *reinterpret_cast<const uint4*>(src + (size_t)row * N_QKV + seg * 8);
        *reinterpret_cast<uint4*>(Ks + row * 72 + seg * 8) =
            *reinterpret_cast<const uint4*>(src + (size_t)row * N_QKV + 512 + seg * 8);
        *reinterpret_cast<uint4*>(Vs + row * 72 + seg * 8) =
            *reinterpret_cast<const uint4*>(src + (size_t)row * N_QKV + 1024 + seg * 8);
    }
    __syncthreads();

    const uint32_t qB = smem_u32(Qs) + (((warp * 16 + (lane & 15)) * 72 + ((lane >> 4) << 3)) << 1);
    const uint32_t kB = smem_u32(Ks) + (((((lane >> 4) & 1) * 8 + (lane & 7)) * 72 + (((lane >> 3) & 1) << 3)) << 1);
    const uint32_t vB = smem_u32(Vs) + ((((lane & 7) + ((lane >> 3) & 1) * 8) * 72 + ((lane >> 4) & 1) * 8) << 1);

    float sc[8][4];
    #pragma unroll
    for (int nt = 0; nt < 8; nt++) { sc[nt][0]=0.f; sc[nt][1]=0.f; sc[nt][2]=0.f; sc[nt][3]=0.f; }
    #pragma unroll
    for (int ks = 0; ks < 4; ks++) {
        uint32_t a[4], bb[4][4];
        ldsm4(a, qB + ((ks * 16) << 1));
        #pragma unroll
        for (int p = 0; p < 4; p++)
            ldsm4(bb[p], kB + (((p * 16) * 72 + ks * 16) << 1));
        #pragma unroll
        for (int nt = 0; nt < 8; nt++)
            mma16816(sc[nt], a[0], a[1], a[2], a[3],
                     bb[nt >> 1][(nt & 1) * 2], bb[nt >> 1][(nt & 1) * 2 + 1]);
    }

    float mx0 = -1e30f, mx1 = -1e30f;
    #pragma unroll
    for (int nt = 0; nt < 8; nt++) {
        mx0 = fmaxf(mx0, fmaxf(sc[nt][0], sc[nt][1]));
        mx1 = fmaxf(mx1, fmaxf(sc[nt][2], sc[nt][3]));
    }
    mx0 = fmaxf(mx0, __shfl_xor_sync(0xffffffff, mx0, 1));
    mx0 = fmaxf(mx0, __shfl_xor_sync(0xffffffff, mx0, 2));
    mx1 = fmaxf(mx1, __shfl_xor_sync(0xffffffff, mx1, 1));
    mx1 = fmaxf(mx1, __shfl_xor_sync(0xffffffff, mx1, 2));
    float s0 = 0.f, s1 = 0.f;
    #pragma unroll
    for (int nt = 0; nt < 8; nt++) {
        sc[nt][0] = __expf((sc[nt][0] - mx0) * SCALE_);
        sc[nt][1] = __expf((sc[nt][1] - mx0) * SCALE_);
        sc[nt][2] = __expf((sc[nt][2] - mx1) * SCALE_);
        sc[nt][3] = __expf((sc[nt][3] - mx1) * SCALE_);
        s0 += sc[nt][0] + sc[nt][1];
        s1 += sc[nt][2] + sc[nt][3];
    }
    s0 += __shfl_xor_sync(0xffffffff, s0, 1);
    s0 += __shfl_xor_sync(0xffffffff, s0, 2);
    s1 += __shfl_xor_sync(0xffffffff, s1, 1);
    s1 += __shfl_xor_sync(0xffffffff, s1, 2);
    const float i0 = 1.f / s0, i1 = 1.f / s1;

    uint32_t pa[8][2];
    #pragma unroll
    for (int nt = 0; nt < 8; nt++) {
        pa[nt][0] = pack_bf16(sc[nt][0] * i0, sc[nt][1] * i0);
        pa[nt][1] = pack_bf16(sc[nt][2] * i1, sc[nt][3] * i1);
    }

    float oc[8][4];
    #pragma unroll
    for (int nt = 0; nt < 8; nt++) { oc[nt][0]=0.f; oc[nt][1]=0.f; oc[nt][2]=0.f; oc[nt][3]=0.f; }
    #pragma unroll
    for (int ks = 0; ks < 4; ks++) {
        uint32_t bb[4][4];
        #pragma unroll
        for (int p = 0; p < 4; p++)
            ldsm4t(bb[p], vB + (((ks * 16) * 72 + p * 16) << 1));
        uint32_t a0 = pa[2 * ks][0], a1 = pa[2 * ks][1];
        uint32_t a2 = pa[2 * ks + 1][0], a3 = pa[2 * ks + 1][1];
        #pragma unroll
        for (int nt = 0; nt < 8; nt++)
            mma16816(oc[nt], a0, a1, a2, a3,
                     bb[nt >> 1][(nt & 1) * 2], bb[nt >> 1][(nt & 1) * 2 + 1]);
    }

    const int r0 = warp * 16 + g;
    __nv_bfloat16* dst = g_o + (size_t)(n * 64) * C_ + h * 64;
    #pragma unroll
    for (int nt = 0; nt < 8; nt++) {
        int dcol = nt * 8 + 2 * tg;
        *reinterpret_cast<uint32_t*>(dst + (size_t)r0 * C_ + dcol)       = pack_bf16(oc[nt][0], oc[nt][1]);
        *reinterpret_cast<uint32_t*>(dst + (size_t)(r0 + 8) * C_ + dcol) = pack_bf16(oc[nt][2], oc[nt][3]);
    }
}

// ---------------- launch ----------------
extern "C" void kernel_launch(void* const* d_in, const int* in_sizes, int n_in,
                              void* d_out, int out_size) {
    const float* x  = (const float*)d_in[0];
    const float* wq = (const float*)d_in[1];
    const float* bq = (const float*)d_in[2];
    const float* wk = (const float*)d_in[3];
    const float* bk = (const float*)d_in[4];
    const float* wv = (const float*)d_in[5];
    const float* bv = (const float*)d_in[6];
    const float* wo = (const float*)d_in[7];
    const float* bo = (const float*)d_in[8];
    float* out = (float*)d_out;

    cudaFuncSetAttribute(qkv_kernel,  cudaFuncAttributeMaxDynamicSharedMemorySize, SMEM_DYN);
    cudaFuncSetAttribute(proj_kernel, cudaFuncAttributeMaxDynamicSharedMemorySize, SMEM_DYN);

    convert_weights<<<(C_ * C_ + 255) / 256, 256>>>(wq, wk, wv, wo);
    gather_kernel<<<(MROWS * C_ / 4) / 256, 256>>>(x);
    dim3 g1(12, 256);
    qkv_kernel<<<g1, 256, SMEM_DYN>>>(bq, bk, bv);
    attn_kernel<<<NWIN * NH_, 128>>>();
    dim3 g3(4, 256);
    proj_kernel<<<g3, 256, SMEM_DYN>>>(x, bo, out);
}